// round 14
// baseline (speedup 1.0000x reference)
#include <cuda_runtime.h>
#include <cuda_bf16.h>

// RWKV single-token inference, fp32 — persistent kernel (148x256).
// R14: dynamic work-stealing (per-phase atomic counters) + cross-barrier
// cp.async queue (depth 3/warp). Straggler spread -> one-unit tail.
// D=1024, H=4096, L=24, V=50277.

#define D    1024
#define HD   4096
#define NL   24
#define NV   50277
#define GRID 148
#define NTH  256
#define NWARP 8

#define SBUF_F   4096                  // 16KB shared vector region (floats)
#define WSLOT_F  1024                  // 4KB slot
#define SMEM_DYN ((SBUF_F + NWARP * 3 * WSLOT_F) * 4)   // 112KB

__device__ __align__(16) float g_x[D];
__device__ __align__(16) float g_kvr[3 * D];
__device__ __align__(16) float g_kk[HD];
__device__ __align__(16) float g_r2[D];
__device__ __align__(16) float g_state_scratch[NL * 5 * D];
__device__ unsigned g_count;
__device__ unsigned g_gen;
__device__ unsigned g_ctr[128];   // 4 per layer (A,B,C,D) + [96]=head

__device__ __forceinline__ float warp_sum(float s) {
#pragma unroll
    for (int o = 16; o > 0; o >>= 1) s += __shfl_xor_sync(0xffffffffu, s, o);
    return s;
}

// Grid barrier (148 co-resident blocks).
__device__ __forceinline__ void grid_barrier() {
    __syncthreads();
    if (threadIdx.x == 0) {
        unsigned gen;
        asm volatile("ld.global.relaxed.gpu.u32 %0, [%1];" : "=r"(gen) : "l"(&g_gen));
        unsigned old;
        asm volatile("atom.global.add.acq_rel.gpu.u32 %0, [%1], 1;"
                     : "=r"(old) : "l"(&g_count) : "memory");
        if (old == GRID - 1) {
            asm volatile("st.global.relaxed.gpu.u32 [%0], %1;" :: "l"(&g_count), "r"(0u) : "memory");
            asm volatile("st.global.release.gpu.u32 [%0], %1;" :: "l"(&g_gen), "r"(gen + 1u) : "memory");
        } else {
            unsigned cur;
            do {
                __nanosleep(20);
                asm volatile("ld.global.acquire.gpu.u32 %0, [%1];" : "=r"(cur) : "l"(&g_gen) : "memory");
            } while (cur == gen);
        }
    }
    __syncthreads();
}

// 4KB row -> shared via cp.async (8x16B per lane).
__device__ __forceinline__ void cpa_row(unsigned dst, const float* __restrict__ src, int lane) {
    unsigned d = dst + (unsigned)lane * 16u;
    const char* s = (const char*)src + lane * 16;
#pragma unroll
    for (int j = 0; j < 8; j++)
        asm volatile("cp.async.cg.shared.global [%0], [%1], 16;"
                     :: "r"(d + 512u * j), "l"(s + 512 * j) : "memory");
}
#define CPA_COMMIT() asm volatile("cp.async.commit_group;" ::: "memory")
#define CPA_WAIT(n)  asm volatile("cp.async.wait_group %0;" :: "n"(n) : "memory")

__device__ __forceinline__ int claimu(unsigned* c, int lane, unsigned inc) {
    int u = 0;
    if (lane == 0) u = (int)atomicAdd(c, inc);
    return __shfl_sync(0xffffffffu, u, 0);
}

__device__ __forceinline__ float dot_ss(const float4* __restrict__ w4,
                                        const float4* __restrict__ v4, int lane) {
    float s = 0.f;
#pragma unroll
    for (int j = 0; j < 8; j++) {
        float4 a = w4[lane + 32 * j];
        float4 b = v4[lane + 32 * j];
        s = fmaf(a.x, b.x, s); s = fmaf(a.y, b.y, s);
        s = fmaf(a.z, b.z, s); s = fmaf(a.w, b.w, s);
    }
    return s;
}

// Fused single-pass LN over g_x (sum+sumsq in one reduction).
__device__ __forceinline__ void ln_fused(const float* __restrict__ w,
                                         const float* __restrict__ b,
                                         float* sred, float out[4]) {
    int t = threadIdx.x, warp = t >> 5, lane = t & 31;
    float4 xv = __ldcg((const float4*)g_x + t);
    float s = xv.x + xv.y + xv.z + xv.w;
    float q = xv.x * xv.x + xv.y * xv.y + xv.z * xv.z + xv.w * xv.w;
    __syncthreads();
#pragma unroll
    for (int o = 16; o > 0; o >>= 1) {
        s += __shfl_xor_sync(0xffffffffu, s, o);
        q += __shfl_xor_sync(0xffffffffu, q, o);
    }
    if (lane == 0) { sred[warp] = s; sred[NWARP + warp] = q; }
    __syncthreads();
    float ts = 0.f, tq = 0.f;
#pragma unroll
    for (int ww = 0; ww < NWARP; ww++) { ts += sred[ww]; tq += sred[NWARP + ww]; }
    float mu = ts * (1.f / D);
    float var = tq * (1.f / D) - mu * mu;
    float rstd = rsqrtf(var + 1e-5f);
    float xa[4]; *(float4*)xa = xv;
    float wa[4], ba[4];
    *(float4*)wa = ((const float4*)w)[t];
    *(float4*)ba = ((const float4*)b)[t];
#pragma unroll
    for (int c = 0; c < 4; c++) out[c] = (xa[c] - mu) * rstd * wa[c] + ba[c];
}

__global__ __launch_bounds__(NTH, 1) void rwkv_fused(
    const int* __restrict__ token, const float* __restrict__ state,
    const float* __restrict__ emb,
    const float* __restrict__ ln0_w, const float* __restrict__ ln0_b,
    const float* __restrict__ ln1_w, const float* __restrict__ ln1_b,
    const float* __restrict__ ln2_w, const float* __restrict__ ln2_b,
    const float* __restrict__ kw, const float* __restrict__ vw,
    const float* __restrict__ rw, const float* __restrict__ ow,
    const float* __restrict__ mk, const float* __restrict__ mv,
    const float* __restrict__ mr,
    const float* __restrict__ tf, const float* __restrict__ td,
    const float* __restrict__ fkw, const float* __restrict__ fvw,
    const float* __restrict__ frw,
    const float* __restrict__ fmk, const float* __restrict__ fmr,
    const float* __restrict__ lnw, const float* __restrict__ lnb,
    const float* __restrict__ head,
    float* __restrict__ logits, float* __restrict__ state_out) {
    __shared__ float sred[2 * NWARP];
    extern __shared__ __align__(16) float dsm[];
    float* s_buf = dsm;                                             // 16KB
    float* slots = dsm + SBUF_F + (threadIdx.x >> 5) * (3 * WSLOT_F);
    const unsigned slu = (unsigned)__cvta_generic_to_shared(slots);

    const int t = threadIdx.x, warp = t >> 5, lane = t & 31, bid = blockIdx.x;

#define SLOTI(i) ((const float4*)(slots + (i) * WSLOT_F))

    // Queue state (depth 3, FIFO; carries across barriers).
    int qu[3];
    int qh = 0, qt = 0, qn = 0;

#define FILL3(EXH, CIDX, NU, SRCEXPR) \
    while (!(EXH) && qn < 3) { \
        int u_ = claimu(&g_ctr[CIDX], lane, 1u); \
        if (u_ >= (NU)) { (EXH) = true; break; } \
        qu[qt] = u_; \
        cpa_row(slu + (unsigned)qt * 4096u, (SRCEXPR), lane); \
        CPA_COMMIT(); \
        qt = (qt == 2) ? 0 : qt + 1; qn++; \
    }
#define WAIT_OLDEST() do { if (qn >= 3) { CPA_WAIT(2); } \
                           else if (qn == 2) { CPA_WAIT(1); } \
                           else { CPA_WAIT(0); } } while (0)
#define POPQ() do { qh = (qh == 2) ? 0 : qh + 1; qn--; } while (0)

    // Zero counters 1..96 (A0 = ctr[0] is reset late in the previous launch).
    if (bid == 0 && t >= 1 && t <= 96) g_ctr[t] = 0u;

    // ---- embed: block 0 computes g_x = LN0(emb[token]) ----
    if (bid == 0) {
        float4 xv = ((const float4*)(emb + (size_t)token[0] * D))[t];
        float s = xv.x + xv.y + xv.z + xv.w;
        float q = xv.x * xv.x + xv.y * xv.y + xv.z * xv.z + xv.w * xv.w;
#pragma unroll
        for (int o = 16; o > 0; o >>= 1) {
            s += __shfl_xor_sync(0xffffffffu, s, o);
            q += __shfl_xor_sync(0xffffffffu, q, o);
        }
        if (lane == 0) { sred[warp] = s; sred[NWARP + warp] = q; }
        __syncthreads();
        float ts = 0.f, tq = 0.f;
#pragma unroll
        for (int ww = 0; ww < NWARP; ww++) { ts += sred[ww]; tq += sred[NWARP + ww]; }
        float mu = ts * (1.f / D);
        float var = tq * (1.f / D) - mu * mu;
        float rstd = rsqrtf(var + 1e-5f);
        float4 wv = ((const float4*)ln0_w)[t];
        float4 bv = ((const float4*)ln0_b)[t];
        float4 o;
        o.x = (xv.x - mu) * rstd * wv.x + bv.x;
        o.y = (xv.y - mu) * rstd * wv.y + bv.y;
        o.z = (xv.z - mu) * rstd * wv.z + bv.z;
        o.w = (xv.w - mu) * rstd * wv.w + bv.w;
        ((float4*)g_x)[t] = o;
    }

#define SRCA(LW) ((((u_) < 1024) ? kw : ((u_) < 2048) ? vw : rw) \
                  + (LW) + (size_t)((u_) & 1023) * D)

    // Pre-fill layer-0 phase A.
    bool exhA = false;
    FILL3(exhA, 0, 3 * D, SRCA((size_t)0));

    for (int l = 0; l < NL; l++) {
        const size_t lo = (size_t)l * D;
        const size_t loW = lo * D;
        const size_t sb = (size_t)l * 5 * D;
        const float* fk_base = fkw + (size_t)l * HD * D;
        const float* fr_base = frw + loW;
        const float* fv_base = fvw + (size_t)l * D * HD;

        // ================= Phase A: k/v/r matvecs =================
        grid_barrier();   // g_x final
        {
            float xn4[4];
            ln_fused(ln1_w + lo, ln1_b + lo, sred, xn4);
            float mka[4], mva[4], mra[4], sxa[4];
            *(float4*)mka = ((const float4*)(mk + lo))[t];
            *(float4*)mva = ((const float4*)(mv + lo))[t];
            *(float4*)mra = ((const float4*)(mr + lo))[t];
            *(float4*)sxa = ((const float4*)(state + sb + D))[t];  // sx_att
            int base = 4 * t;
#pragma unroll
            for (int c = 0; c < 4; c++) {
                float xn = xn4[c];
                s_buf[base + c]         = xn * mka[c] + sxa[c] * (1.f - mka[c]);
                s_buf[D + base + c]     = xn * mva[c] + sxa[c] * (1.f - mva[c]);
                s_buf[2 * D + base + c] = xn * mra[c] + sxa[c] * (1.f - mra[c]);
                if (bid == 0) state_out[sb + D + base + c] = xn;   // state row 1
            }
            __syncthreads();

            while (qn > 0) {
                WAIT_OLDEST();
                int u = qu[qh];
                const float4* x4 = (const float4*)s_buf + ((u >> 10) << 8);
                float s = warp_sum(dot_ss(SLOTI(qh), x4, lane));
                if (lane == 0) g_kvr[u] = s;
                POPQ();
                FILL3(exhA, 4 * l, 3 * D, SRCA(loW));
            }
        }
        // pre-fill phase B
        bool exhB = false;
        FILL3(exhB, 4 * l + 1, D, ow + loW + (size_t)u_ * D);

        // ================= Phase B: x += ow @ rwkv =================
        grid_barrier();   // g_kvr complete
        if (l == 0 && bid == 0 && t == 0) g_ctr[0] = 0u;   // reset A0 for next launch
        {
            // Redundant per-block WKV epilogue from g_kvr (cheap).
            float ka[4], va[4], ra[4], aa[4], bb[4], pp[4], tfa[4], tda[4];
            *(float4*)ka = __ldcg((const float4*)g_kvr + t);
            *(float4*)va = __ldcg((const float4*)(g_kvr + D) + t);
            *(float4*)ra = __ldcg((const float4*)(g_kvr + 2 * D) + t);
            *(float4*)aa = ((const float4*)(state + sb + 2 * D))[t];
            *(float4*)bb = ((const float4*)(state + sb + 3 * D))[t];
            *(float4*)pp = ((const float4*)(state + sb + 4 * D))[t];
            *(float4*)tfa = ((const float4*)(tf + lo))[t];
            *(float4*)tda = ((const float4*)(td + lo))[t];
            int base = 4 * t;
#pragma unroll
            for (int c = 0; c < 4; c++) {
                float k = ka[c], v = va[c];
                float rs = 1.f / (1.f + expf(-ra[c]));
                float ww = tfa[c] + k;
                float qq = fmaxf(pp[c], ww);
                float e1 = expf(pp[c] - qq);
                float e2 = expf(ww - qq);
                s_buf[base + c] = rs * (e1 * aa[c] + e2 * v) / (e1 * bb[c] + e2);
                if (bid == 0) {
                    float ww2 = pp[c] + tda[c];
                    float qq2 = fmaxf(ww2, k);
                    float e1b = expf(ww2 - qq2);
                    float e2b = expf(k - qq2);
                    state_out[sb + 2 * D + base + c] = e1b * aa[c] + e2b * v;
                    state_out[sb + 3 * D + base + c] = e1b * bb[c] + e2b;
                    state_out[sb + 4 * D + base + c] = qq2;
                }
            }
            __syncthreads();

            while (qn > 0) {
                WAIT_OLDEST();
                int u = qu[qh];
                float s = warp_sum(dot_ss(SLOTI(qh), (const float4*)s_buf, lane));
                if (lane == 0) g_x[u] = __ldcg(g_x + u) + s;
                POPQ();
                FILL3(exhB, 4 * l + 1, D, ow + loW + (size_t)u_ * D);
            }
        }
        // pre-fill phase C
        bool exhC = false;
        FILL3(exhC, 4 * l + 2, HD + D,
              (u_ < HD) ? fk_base + (size_t)u_ * D : fr_base + (size_t)(u_ - HD) * D);

        // ================= Phase C: channel mix 1 =================
        grid_barrier();   // g_x updated
        {
            float xn4[4];
            ln_fused(ln2_w + lo, ln2_b + lo, sred, xn4);
            float mka[4], mra[4], sxa[4];
            *(float4*)mka = ((const float4*)(fmk + lo))[t];
            *(float4*)mra = ((const float4*)(fmr + lo))[t];
            *(float4*)sxa = ((const float4*)(state + sb))[t];      // sx_ffn
            int base = 4 * t;
#pragma unroll
            for (int c = 0; c < 4; c++) {
                float xn = xn4[c];
                s_buf[base + c]     = xn * mka[c] + sxa[c] * (1.f - mka[c]);
                s_buf[D + base + c] = xn * mra[c] + sxa[c] * (1.f - mra[c]);
                if (bid == 0) state_out[sb + base + c] = xn;       // state row 0
            }
            __syncthreads();

            while (qn > 0) {
                WAIT_OLDEST();
                int u = qu[qh];
                const float4* x4 = (u < HD) ? (const float4*)s_buf
                                            : (const float4*)s_buf + 256;
                float s = warp_sum(dot_ss(SLOTI(qh), x4, lane));
                if (lane == 0) {
                    if (u < HD) { float rl = fmaxf(s, 0.f); g_kk[u] = rl * rl; }
                    else g_r2[u - HD] = 1.f / (1.f + expf(-s));
                }
                POPQ();
                FILL3(exhC, 4 * l + 2, HD + D,
                      (u_ < HD) ? fk_base + (size_t)u_ * D : fr_base + (size_t)(u_ - HD) * D);
            }
        }
        // pre-claim one D row, issue its first 3 chunks
        int rD = claimu(&g_ctr[4 * l + 3], lane, 1u);
        if (rD < D) {
            const float* src = fv_base + (size_t)rD * HD;
            cpa_row(slu,          src,        lane); CPA_COMMIT();
            cpa_row(slu + 4096u,  src + 1024, lane); CPA_COMMIT();
            cpa_row(slu + 8192u,  src + 2048, lane); CPA_COMMIT();
        }

        // ================= Phase D: x += r2 * (fvw @ kk) =================
        grid_barrier();   // g_kk, g_r2 complete
        {
#pragma unroll
            for (int j = 0; j < 4; j++)
                ((float4*)s_buf)[t + NTH * j] = __ldcg((const float4*)g_kk + t + NTH * j);
            __syncthreads();
            const float4* kk4 = (const float4*)s_buf;
            int sbslot = 0;
            while (rD < D) {
                const float* src = fv_base + (size_t)rD * HD;
                int s0 = sbslot, s1 = (s0 == 2) ? 0 : s0 + 1, s2 = (s1 == 2) ? 0 : s1 + 1;
                CPA_WAIT(2);
                float s = dot_ss(SLOTI(s0), kk4, lane);
                cpa_row(slu + (unsigned)s0 * 4096u, src + 3072, lane); CPA_COMMIT();
                CPA_WAIT(2);
                s += dot_ss(SLOTI(s1), kk4 + 256, lane);
                int rn = claimu(&g_ctr[4 * l + 3], lane, 1u);
                const float* nsrc = fv_base + (size_t)rn * HD;
                if (rn < D) cpa_row(slu + (unsigned)s1 * 4096u, nsrc, lane);
                CPA_COMMIT();
                CPA_WAIT(2);
                s += dot_ss(SLOTI(s2), kk4 + 512, lane);
                if (rn < D) cpa_row(slu + (unsigned)s2 * 4096u, nsrc + 1024, lane);
                CPA_COMMIT();
                CPA_WAIT(2);
                s += dot_ss(SLOTI(s0), kk4 + 768, lane);
                if (rn < D) cpa_row(slu + (unsigned)s0 * 4096u, nsrc + 2048, lane);
                CPA_COMMIT();
                s = warp_sum(s);
                if (lane == 0) g_x[rD] = __ldcg(g_x + rD) + __ldcg(g_r2 + rD) * s;
                sbslot = s1;
                rD = rn;
            }
        }
        // queue is empty here; pre-fill next phase
        qh = qt = 0; qn = 0;
        if (l + 1 < NL) {
            exhA = false;
            FILL3(exhA, 4 * (l + 1), 3 * D, SRCA((size_t)(l + 1) * D * D));
        }
    }

    // ================= Head: logits = head @ LN(x) =================
    bool exhH = false;
    int hbase = 0, hleft = 0;
#define FILLH() \
    while (!exhH && qn < 3) { \
        if (hleft == 0) { \
            hbase = claimu(&g_ctr[96], lane, 4u); \
            if (hbase >= NV) { exhH = true; break; } \
            hleft = (NV - hbase < 4) ? (NV - hbase) : 4; \
        } \
        qu[qt] = hbase; \
        cpa_row(slu + (unsigned)qt * 4096u, head + (size_t)hbase * D, lane); \
        CPA_COMMIT(); \
        hbase++; hleft--; qt = (qt == 2) ? 0 : qt + 1; qn++; \
    }
    FILLH();
    grid_barrier();   // g_x final
    {
        float xn4[4];
        ln_fused(lnw, lnb, sred, xn4);
        int base = 4 * t;
#pragma unroll
        for (int c = 0; c < 4; c++) s_buf[base + c] = xn4[c];
        __syncthreads();

        const float4* x4 = (const float4*)s_buf;
        while (qn > 0) {
            WAIT_OLDEST();
            int v = qu[qh];
            float s = warp_sum(dot_ss(SLOTI(qh), x4, lane));
            POPQ();
            FILLH();
            if (lane == 0) logits[v] = s;
        }
    }
}

// ---------------------------------------------------------------------------
extern "C" void kernel_launch(void* const* d_in, const int* in_sizes, int n_in,
                              void* d_out, int out_size) {
    const int*   token     = (const int*)d_in[0];
    const float* state     = (const float*)d_in[1];
    const float* emb       = (const float*)d_in[2];
    const float* ln0_w     = (const float*)d_in[3];
    const float* ln0_b     = (const float*)d_in[4];
    const float* ln1_w     = (const float*)d_in[5];
    const float* ln1_b     = (const float*)d_in[6];
    const float* ln2_w     = (const float*)d_in[7];
    const float* ln2_b     = (const float*)d_in[8];
    const float* att_key   = (const float*)d_in[9];
    const float* att_value = (const float*)d_in[10];
    const float* att_recep = (const float*)d_in[11];
    const float* att_out   = (const float*)d_in[12];
    const float* tm_k      = (const float*)d_in[13];
    const float* tm_v      = (const float*)d_in[14];
    const float* tm_r      = (const float*)d_in[15];
    const float* t_first   = (const float*)d_in[16];
    const float* t_decay   = (const float*)d_in[17];
    const float* ffn_key   = (const float*)d_in[18];
    const float* ffn_value = (const float*)d_in[19];
    const float* ffn_recep = (const float*)d_in[20];
    const float* ffn_tm_k  = (const float*)d_in[21];
    const float* ffn_tm_r  = (const float*)d_in[22];
    const float* lnout_w   = (const float*)d_in[23];
    const float* lnout_b   = (const float*)d_in[24];
    const float* head      = (const float*)d_in[25];

    float* out = (float*)d_out;
    float* logits = out;
    float* state_out;
    if (out_size >= NV + NL * 5 * D) {
        state_out = out + NV;
    } else {
        void* p = nullptr;
        cudaGetSymbolAddress(&p, g_state_scratch);
        state_out = (float*)p;
    }

    static bool attr_set = false;
    if (!attr_set) {
        cudaFuncSetAttribute(rwkv_fused, cudaFuncAttributeMaxDynamicSharedMemorySize,
                             SMEM_DYN);
        attr_set = true;
    }

    rwkv_fused<<<GRID, NTH, SMEM_DYN>>>(token, state, emb, ln0_w, ln0_b,
                                        ln1_w, ln1_b, ln2_w, ln2_b,
                                        att_key, att_value, att_recep, att_out,
                                        tm_k, tm_v, tm_r, t_first, t_decay,
                                        ffn_key, ffn_value, ffn_recep,
                                        ffn_tm_k, ffn_tm_r,
                                        lnout_w, lnout_b, head,
                                        logits, state_out);
}

// round 16
// speedup vs baseline: 1.3702x; 1.3702x over previous
#include <cuda_runtime.h>
#include <cuda_bf16.h>

// RWKV single-token inference, fp32 — persistent kernel (148x256).
// R16 (= R15 fixed): block-cooperative 64KB-chunk streaming via cp.async.bulk
// (4x16KB per chunk), 2-deep double buffer, static chunk ownership.
// D=1024, H=4096, L=24, V=50277.

#define D    1024
#define HD   4096
#define NL   24
#define NV   50277
#define GRID 148
#define NTH  256
#define NWARP 8

#define SVEC_F   4096                 // 16KB vector staging (floats)
#define CH_F     16384                // 64KB chunk (floats)
#define SMEM_DYN ((SVEC_F + 2 * CH_F) * 4)   // 147456 B

__device__ __align__(16) float g_x[D];
__device__ __align__(16) float g_kvr[3 * D];
__device__ __align__(16) float g_kk[HD];
__device__ __align__(16) float g_r2[D];
__device__ __align__(16) float g_state_scratch[NL * 5 * D];
__device__ unsigned g_count;
__device__ unsigned g_gen;

__device__ __forceinline__ float warp_sum(float s) {
#pragma unroll
    for (int o = 16; o > 0; o >>= 1) s += __shfl_xor_sync(0xffffffffu, s, o);
    return s;
}

// Grid barrier (148 co-resident blocks).
__device__ __forceinline__ void grid_barrier() {
    __syncthreads();
    if (threadIdx.x == 0) {
        unsigned gen;
        asm volatile("ld.global.relaxed.gpu.u32 %0, [%1];" : "=r"(gen) : "l"(&g_gen));
        unsigned old;
        asm volatile("atom.global.add.acq_rel.gpu.u32 %0, [%1], 1;"
                     : "=r"(old) : "l"(&g_count) : "memory");
        if (old == GRID - 1) {
            asm volatile("st.global.relaxed.gpu.u32 [%0], %1;" :: "l"(&g_count), "r"(0u) : "memory");
            asm volatile("st.global.release.gpu.u32 [%0], %1;" :: "l"(&g_gen), "r"(gen + 1u) : "memory");
        } else {
            unsigned cur;
            do {
                __nanosleep(20);
                asm volatile("ld.global.acquire.gpu.u32 %0, [%1];" : "=r"(cur) : "l"(&g_gen) : "memory");
            } while (cur == gen);
        }
    }
    __syncthreads();
}

__device__ __forceinline__ void mbar_wait(unsigned mbar, int phase) {
    asm volatile(
        "{\n\t.reg .pred P;\n"
        "WAIT_%=:\n\t"
        "mbarrier.try_wait.parity.acquire.cta.shared::cta.b64 P, [%0], %1, 0x989680;\n\t"
        "@P bra DONE_%=;\n\t"
        "bra WAIT_%=;\n"
        "DONE_%=:\n\t}"
        :: "r"(mbar), "r"((unsigned)phase) : "memory");
}

// Issue one chunk (nbytes) as 16KB bulk copies; single expect_tx. t==0 only.
__device__ __forceinline__ void issue_chunk(unsigned sbuf, const float* __restrict__ src,
                                            unsigned nbytes, unsigned mbar) {
    asm volatile("mbarrier.arrive.expect_tx.shared.b64 _, [%0], %1;"
                 :: "r"(mbar), "r"(nbytes) : "memory");
    const char* s = (const char*)src;
    for (unsigned off = 0; off < nbytes; off += 16384u) {
        unsigned sz = nbytes - off;
        if (sz > 16384u) sz = 16384u;
        asm volatile("cp.async.bulk.shared::cluster.global.mbarrier::complete_tx::bytes "
                     "[%0], [%1], %2, [%3];"
                     :: "r"(sbuf + off), "l"(s + off), "r"(sz), "r"(mbar) : "memory");
    }
}

// 1024-float dot (weights + vector both in shared).
__device__ __forceinline__ float dot_ss(const float4* __restrict__ w4,
                                        const float4* __restrict__ v4, int lane) {
    float s = 0.f;
#pragma unroll
    for (int j = 0; j < 8; j++) {
        float4 a = w4[lane + 32 * j];
        float4 b = v4[lane + 32 * j];
        s = fmaf(a.x, b.x, s); s = fmaf(a.y, b.y, s);
        s = fmaf(a.z, b.z, s); s = fmaf(a.w, b.w, s);
    }
    return s;
}
// 2048-float dot.
__device__ __forceinline__ float dot16(const float4* __restrict__ w4,
                                       const float4* __restrict__ v4, int lane) {
    float s = 0.f;
#pragma unroll
    for (int j = 0; j < 16; j++) {
        float4 a = w4[lane + 32 * j];
        float4 b = v4[lane + 32 * j];
        s = fmaf(a.x, b.x, s); s = fmaf(a.y, b.y, s);
        s = fmaf(a.z, b.z, s); s = fmaf(a.w, b.w, s);
    }
    return s;
}

// Fused single-pass LN over g_x.
__device__ __forceinline__ void ln_fused(const float* __restrict__ w,
                                         const float* __restrict__ b,
                                         float* sred, float out[4]) {
    int t = threadIdx.x;
    int warp = t >> 5;
    int lane = t & 31;
    float4 xv = __ldcg((const float4*)g_x + t);
    float s = xv.x + xv.y + xv.z + xv.w;
    float q = xv.x * xv.x + xv.y * xv.y + xv.z * xv.z + xv.w * xv.w;
    __syncthreads();
#pragma unroll
    for (int o = 16; o > 0; o >>= 1) {
        s += __shfl_xor_sync(0xffffffffu, s, o);
        q += __shfl_xor_sync(0xffffffffu, q, o);
    }
    if (lane == 0) { sred[warp] = s; sred[NWARP + warp] = q; }
    __syncthreads();
    float ts = 0.f, tq = 0.f;
#pragma unroll
    for (int ww = 0; ww < NWARP; ww++) { ts += sred[ww]; tq += sred[NWARP + ww]; }
    float mu = ts * (1.f / D);
    float var = tq * (1.f / D) - mu * mu;
    float rstd = rsqrtf(var + 1e-5f);
    float xa[4]; *(float4*)xa = xv;
    float wa[4], ba[4];
    *(float4*)wa = ((const float4*)w)[t];
    *(float4*)ba = ((const float4*)b)[t];
#pragma unroll
    for (int c = 0; c < 4; c++) out[c] = (xa[c] - mu) * rstd * wa[c] + ba[c];
}

__global__ __launch_bounds__(NTH, 1) void rwkv_fused(
    const int* __restrict__ token, const float* __restrict__ state,
    const float* __restrict__ emb,
    const float* __restrict__ ln0_w, const float* __restrict__ ln0_b,
    const float* __restrict__ ln1_w, const float* __restrict__ ln1_b,
    const float* __restrict__ ln2_w, const float* __restrict__ ln2_b,
    const float* __restrict__ kw, const float* __restrict__ vw,
    const float* __restrict__ rw, const float* __restrict__ ow,
    const float* __restrict__ mk, const float* __restrict__ mv,
    const float* __restrict__ mr,
    const float* __restrict__ tf, const float* __restrict__ td,
    const float* __restrict__ fkw, const float* __restrict__ fvw,
    const float* __restrict__ frw,
    const float* __restrict__ fmk, const float* __restrict__ fmr,
    const float* __restrict__ lnw, const float* __restrict__ lnb,
    const float* __restrict__ head,
    float* __restrict__ logits, float* __restrict__ state_out) {
    __shared__ float sred[2 * NWARP];
    __shared__ float s_part[NWARP];
    __shared__ unsigned long long mbars[2];
    extern __shared__ __align__(16) float dsm[];
    float* s_vec = dsm;                       // 16KB
    float* buf0 = dsm + SVEC_F;               // 64KB
    float* buf1 = dsm + SVEC_F + CH_F;        // 64KB

    const int t = threadIdx.x, warp = t >> 5, lane = t & 31, bid = blockIdx.x;
    const unsigned sbu0 = (unsigned)__cvta_generic_to_shared(buf0);
    const unsigned sbu1 = (unsigned)__cvta_generic_to_shared(buf1);
    const unsigned mbu0 = (unsigned)__cvta_generic_to_shared(&mbars[0]);
    const unsigned mbu1 = (unsigned)__cvta_generic_to_shared(&mbars[1]);
    int ph0 = 0, ph1 = 0;

    if (t < 2) {
        unsigned a = (unsigned)__cvta_generic_to_shared(&mbars[t]);
        asm volatile("mbarrier.init.shared.b64 [%0], %1;" :: "r"(a), "r"(1u) : "memory");
    }
    __syncthreads();
    asm volatile("fence.proxy.async.shared::cta;" ::: "memory");

    // ---- embed: block 0 computes g_x = LN0(emb[token]) ----
    if (bid == 0) {
        float4 xv = ((const float4*)(emb + (size_t)token[0] * D))[t];
        float s = xv.x + xv.y + xv.z + xv.w;
        float q = xv.x * xv.x + xv.y * xv.y + xv.z * xv.z + xv.w * xv.w;
#pragma unroll
        for (int o = 16; o > 0; o >>= 1) {
            s += __shfl_xor_sync(0xffffffffu, s, o);
            q += __shfl_xor_sync(0xffffffffu, q, o);
        }
        if (lane == 0) { sred[warp] = s; sred[NWARP + warp] = q; }
        __syncthreads();
        float ts = 0.f, tq = 0.f;
#pragma unroll
        for (int ww = 0; ww < NWARP; ww++) { ts += sred[ww]; tq += sred[NWARP + ww]; }
        float mu = ts * (1.f / D);
        float var = tq * (1.f / D) - mu * mu;
        float rstd = rsqrtf(var + 1e-5f);
        float4 wv = ((const float4*)ln0_w)[t];
        float4 bv = ((const float4*)ln0_b)[t];
        float4 o;
        o.x = (xv.x - mu) * rstd * wv.x + bv.x;
        o.y = (xv.y - mu) * rstd * wv.y + bv.y;
        o.z = (xv.z - mu) * rstd * wv.z + bv.z;
        o.w = (xv.w - mu) * rstd * wv.w + bv.w;
        ((float4*)g_x)[t] = o;
    }

    // Stream loop machinery (variadic body; parity uniform across block).
#define PROLOGUE(NC, SRC_OF, NB_OF)                                            \
    if (t == 0) {                                                              \
        if (bid < (NC))        issue_chunk(sbu0, SRC_OF(bid), NB_OF(bid), mbu0);\
        if (bid + GRID < (NC)) issue_chunk(sbu1, SRC_OF(bid + GRID), NB_OF(bid + GRID), mbu1); \
    }
#define STREAM(NC, SRC_OF, NB_OF, ...)                                         \
    for (int ci = 0, c = bid; c < (NC); ci++, c += GRID) {                     \
        const float* buf; unsigned sbu_; unsigned mbu_;                        \
        if ((ci & 1) == 0) { mbar_wait(mbu0, ph0); ph0 ^= 1; buf = buf0; sbu_ = sbu0; mbu_ = mbu0; } \
        else               { mbar_wait(mbu1, ph1); ph1 ^= 1; buf = buf1; sbu_ = sbu1; mbu_ = mbu1; } \
        { __VA_ARGS__ }                                                        \
        __syncthreads();                                                       \
        int cn = c + 2 * GRID;                                                 \
        if (cn < (NC) && t == 0) issue_chunk(sbu_, SRC_OF(cn), NB_OF(cn), mbu_);\
    }

#define NB64(c)  (65536u)
#define NB32(c)  (32768u)

    // layer-0 phase A prologue (A: 192 chunks of 16 rows over k|v|r)
#define SRCA(c) ((((c) >> 6) == 0 ? kw : ((c) >> 6) == 1 ? vw : rw) + loW + ((size_t)(((c) & 63) << 4)) * D)
    {
        const size_t loW = 0;
        PROLOGUE(192, SRCA, NB64)
    }

    for (int l = 0; l < NL; l++) {
        const size_t lo = (size_t)l * D;
        const size_t loW = lo * D;
        const size_t sb = (size_t)l * 5 * D;
        const float* fk_base = fkw + (size_t)l * HD * D;
        const float* fv_base = fvw + (size_t)l * D * HD;

        // ================= Phase A: k/v/r matvecs =================
        grid_barrier();   // g_x final
        {
            float xn4[4];
            ln_fused(ln1_w + lo, ln1_b + lo, sred, xn4);
            float mka[4], mva[4], mra[4], sxa[4];
            *(float4*)mka = ((const float4*)(mk + lo))[t];
            *(float4*)mva = ((const float4*)(mv + lo))[t];
            *(float4*)mra = ((const float4*)(mr + lo))[t];
            *(float4*)sxa = ((const float4*)(state + sb + D))[t];  // sx_att
            int base = 4 * t;
#pragma unroll
            for (int c = 0; c < 4; c++) {
                float xn = xn4[c];
                s_vec[base + c]         = xn * mka[c] + sxa[c] * (1.f - mka[c]);
                s_vec[D + base + c]     = xn * mva[c] + sxa[c] * (1.f - mva[c]);
                s_vec[2 * D + base + c] = xn * mra[c] + sxa[c] * (1.f - mra[c]);
                if (bid == 0) state_out[sb + D + base + c] = xn;   // state row 1
            }
            __syncthreads();

            STREAM(192, SRCA, NB64,
                int seg = c >> 6;
                int rb = (c & 63) << 4;
                const float4* vv = (const float4*)(s_vec + (seg << 10));
#pragma unroll
                for (int rr = 0; rr < 2; rr++) {
                    int r = 2 * warp + rr;
                    float s = warp_sum(dot_ss((const float4*)(buf + r * 1024), vv, lane));
                    if (lane == 0) g_kvr[(seg << 10) + rb + r] = s;
                }
            )
        }
        // B prologue: 128 chunks of 8 rows (32KB)
#define SRCB(c) (ow + loW + ((size_t)((c) << 3)) * D)
        PROLOGUE(128, SRCB, NB32)

        // ================= Phase B: WKV epilogue + ow matvec =================
        grid_barrier();   // g_kvr complete
        {
            // Redundant per-block WKV epilogue -> s_vec[0..1023] = r*wkv
            float ka[4], va[4], ra[4], aa[4], bb[4], pp[4], tfa[4], tda[4];
            *(float4*)ka = __ldcg((const float4*)g_kvr + t);
            *(float4*)va = __ldcg((const float4*)(g_kvr + D) + t);
            *(float4*)ra = __ldcg((const float4*)(g_kvr + 2 * D) + t);
            *(float4*)aa = ((const float4*)(state + sb + 2 * D))[t];
            *(float4*)bb = ((const float4*)(state + sb + 3 * D))[t];
            *(float4*)pp = ((const float4*)(state + sb + 4 * D))[t];
            *(float4*)tfa = ((const float4*)(tf + lo))[t];
            *(float4*)tda = ((const float4*)(td + lo))[t];
            int base = 4 * t;
#pragma unroll
            for (int c = 0; c < 4; c++) {
                float k = ka[c];
                float v = va[c];
                float rs = 1.f / (1.f + expf(-ra[c]));
                float ww = tfa[c] + k;
                float qq = fmaxf(pp[c], ww);
                float e1 = expf(pp[c] - qq);
                float e2 = expf(ww - qq);
                s_vec[base + c] = rs * (e1 * aa[c] + e2 * v) / (e1 * bb[c] + e2);
                if (bid == 0) {
                    float ww2 = pp[c] + tda[c];
                    float qq2 = fmaxf(ww2, k);
                    float e1b = expf(ww2 - qq2);
                    float e2b = expf(k - qq2);
                    state_out[sb + 2 * D + base + c] = e1b * aa[c] + e2b * v;
                    state_out[sb + 3 * D + base + c] = e1b * bb[c] + e2b;
                    state_out[sb + 4 * D + base + c] = qq2;
                }
            }
            __syncthreads();

            STREAM(128, SRCB, NB32,
                int rb = c << 3;
                int r = warp;   // 8 rows, 1 per warp
                float s = warp_sum(dot_ss((const float4*)(buf + r * 1024),
                                          (const float4*)s_vec, lane));
                if (lane == 0) g_x[rb + r] = __ldcg(g_x + rb + r) + s;
            )
        }
        // C prologue: 320 chunks (256 fkw + 64 frw), 16 rows each
#define SRCC(c) (((c) < 256) ? fk_base + ((size_t)((c) << 4)) * D \
                             : frw + loW + ((size_t)(((c) - 256) << 4)) * D)
        PROLOGUE(320, SRCC, NB64)

        // ================= Phase C: channel mix 1 =================
        grid_barrier();   // g_x updated
        {
            float xn4[4];
            ln_fused(ln2_w + lo, ln2_b + lo, sred, xn4);
            float mka[4], mra[4], sxa[4];
            *(float4*)mka = ((const float4*)(fmk + lo))[t];
            *(float4*)mra = ((const float4*)(fmr + lo))[t];
            *(float4*)sxa = ((const float4*)(state + sb))[t];      // sx_ffn
            int base = 4 * t;
#pragma unroll
            for (int c = 0; c < 4; c++) {
                float xn = xn4[c];
                s_vec[base + c]     = xn * mka[c] + sxa[c] * (1.f - mka[c]);
                s_vec[D + base + c] = xn * mra[c] + sxa[c] * (1.f - mra[c]);
                if (bid == 0) state_out[sb + base + c] = xn;       // state row 0
            }
            __syncthreads();

            STREAM(320, SRCC, NB64,
                bool fk = (c < 256);
                int rb = fk ? (c << 4) : ((c - 256) << 4);
                const float4* vv = fk ? (const float4*)s_vec
                                      : (const float4*)(s_vec + D);
#pragma unroll
                for (int rr = 0; rr < 2; rr++) {
                    int r = 2 * warp + rr;
                    float s = warp_sum(dot_ss((const float4*)(buf + r * 1024), vv, lane));
                    if (lane == 0) {
                        if (fk) { float rl = fmaxf(s, 0.f); g_kk[rb + r] = rl * rl; }
                        else g_r2[rb + r] = 1.f / (1.f + expf(-s));
                    }
                }
            )
        }
        // D prologue: 256 chunks of 4 rows (16KB rows)
#define SRCD(c) (fv_base + ((size_t)((c) << 2)) * HD)
        PROLOGUE(256, SRCD, NB64)

        // ================= Phase D: x += r2 * (fvw @ kk) =================
        grid_barrier();   // g_kk, g_r2 complete
        {
#pragma unroll
            for (int j = 0; j < 4; j++)
                ((float4*)s_vec)[t + NTH * j] = __ldcg((const float4*)g_kk + t + NTH * j);
            __syncthreads();

            STREAM(256, SRCD, NB64,
                int rb = c << 2;
                int r = warp >> 1;
                int hf = warp & 1;
                float s = warp_sum(dot16((const float4*)(buf + r * 4096 + hf * 2048),
                                         (const float4*)(s_vec + hf * 2048), lane));
                if (lane == 0) s_part[warp] = s;
                __syncthreads();
                if (t < 4) {
                    float tot = s_part[2 * t] + s_part[2 * t + 1];
                    int row = rb + t;
                    g_x[row] = __ldcg(g_x + row) + __ldcg(g_r2 + row) * tot;
                }
            )
        }
        // next prologue: layer l+1 phase A
        if (l + 1 < NL) {
            const size_t loW2 = (size_t)(l + 1) * D * D;
#define SRCA2(c) ((((c) >> 6) == 0 ? kw : ((c) >> 6) == 1 ? vw : rw) + loW2 + ((size_t)(((c) & 63) << 4)) * D)
            PROLOGUE(192, SRCA2, NB64)
#undef SRCA2
        }
    }

    // ================= Head: logits = head @ LN(x) =================
#define NCH   3143
#define SRCH(c)  (head + ((size_t)((c) << 4)) * D)
#define NBH(c)   ((unsigned)(((NV - ((c) << 4)) < 16 ? (NV - ((c) << 4)) : 16) * 4096))
    PROLOGUE(NCH, SRCH, NBH)
    grid_barrier();   // g_x final
    {
        float xn4[4];
        ln_fused(lnw, lnb, sred, xn4);
        int base = 4 * t;
#pragma unroll
        for (int c = 0; c < 4; c++) s_vec[base + c] = xn4[c];
        __syncthreads();

        STREAM(NCH, SRCH, NBH,
            int rb = c << 4;
            int cnt = NV - rb;
            if (cnt > 16) cnt = 16;
#pragma unroll
            for (int rr = 0; rr < 2; rr++) {
                int r = 2 * warp + rr;
                if (r < cnt) {
                    float s = warp_sum(dot_ss((const float4*)(buf + r * 1024),
                                              (const float4*)s_vec, lane));
                    if (lane == 0) logits[rb + r] = s;
                }
            }
        )
    }
}

// ---------------------------------------------------------------------------
extern "C" void kernel_launch(void* const* d_in, const int* in_sizes, int n_in,
                              void* d_out, int out_size) {
    const int*   token     = (const int*)d_in[0];
    const float* state     = (const float*)d_in[1];
    const float* emb       = (const float*)d_in[2];
    const float* ln0_w     = (const float*)d_in[3];
    const float* ln0_b     = (const float*)d_in[4];
    const float* ln1_w     = (const float*)d_in[5];
    const float* ln1_b     = (const float*)d_in[6];
    const float* ln2_w     = (const float*)d_in[7];
    const float* ln2_b     = (const float*)d_in[8];
    const float* att_key   = (const float*)d_in[9];
    const float* att_value = (const float*)d_in[10];
    const float* att_recep = (const float*)d_in[11];
    const float* att_out   = (const float*)d_in[12];
    const float* tm_k      = (const float*)d_in[13];
    const float* tm_v      = (const float*)d_in[14];
    const float* tm_r      = (const float*)d_in[15];
    const float* t_first   = (const float*)d_in[16];
    const float* t_decay   = (const float*)d_in[17];
    const float* ffn_key   = (const float*)d_in[18];
    const float* ffn_value = (const float*)d_in[19];
    const float* ffn_recep = (const float*)d_in[20];
    const float* ffn_tm_k  = (const float*)d_in[21];
    const float* ffn_tm_r  = (const float*)d_in[22];
    const float* lnout_w   = (const float*)d_in[23];
    const float* lnout_b   = (const float*)d_in[24];
    const float* head      = (const float*)d_in[25];

    float* out = (float*)d_out;
    float* logits = out;
    float* state_out;
    if (out_size >= NV + NL * 5 * D) {
        state_out = out + NV;
    } else {
        void* p = nullptr;
        cudaGetSymbolAddress(&p, g_state_scratch);
        state_out = (float*)p;
    }

    static bool attr_set = false;
    if (!attr_set) {
        cudaFuncSetAttribute(rwkv_fused, cudaFuncAttributeMaxDynamicSharedMemorySize,
                             SMEM_DYN);
        attr_set = true;
    }

    rwkv_fused<<<GRID, NTH, SMEM_DYN>>>(token, state, emb, ln0_w, ln0_b,
                                        ln1_w, ln1_b, ln2_w, ln2_b,
                                        att_key, att_value, att_recep, att_out,
                                        tm_k, tm_v, tm_r, t_first, t_decay,
                                        ffn_key, ffn_value, ffn_recep,
                                        ffn_tm_k, ffn_tm_r,
                                        lnout_w, lnout_b, head,
                                        logits, state_out);
}